// round 8
// baseline (speedup 1.0000x reference)
#include <cuda_runtime.h>
#include <cstdint>

#define BATCH 512
#define TSTEPS 1024
#define IDIM 64
#define HDIM 128

typedef unsigned long long u64t;

__device__ __forceinline__ u64t ffma2(u64t a, u64t b, u64t c) {
    u64t d;
    asm("fma.rn.f32x2 %0, %1, %2, %3;" : "=l"(d) : "l"(a), "l"(b), "l"(c));
    return d;
}
__device__ __forceinline__ u64t fmul2(u64t a, u64t b) {
    u64t d;
    asm("mul.rn.f32x2 %0, %1, %2;" : "=l"(d) : "l"(a), "l"(b));
    return d;
}
__device__ __forceinline__ u64t pk(float a, float b) {
    u64t r; asm("mov.b64 %0, {%1, %2};" : "=l"(r) : "f"(a), "f"(b)); return r;
}
__device__ __forceinline__ float hadd2(u64t v) {
    float x, y;
    asm("mov.b64 {%0, %1}, %2;" : "=f"(x), "=f"(y) : "l"(v));
    return x + y;
}
__device__ __forceinline__ float tanh_ap(float x) {
    float y; asm("tanh.approx.f32 %0, %1;" : "=f"(y) : "f"(x)); return y;
}

// ---------------------------------------------------------------------------
// Fully fused RNN: 256 CTAs x 256 threads, 2 batch rows/CTA, 2 CTAs/SM.
// Thread tiling: lane=(kq=lane>>3, jl=lane&7); warp w -> j0=w*16+jl, j1=j0+8.
// Per step, per thread: x-projection partials first (no h dependency), then
// 64 hh ffma2 from registers, then a SPLIT butterfly reduce (3 shfl, each of
// the 32 lanes finishes exactly one (j,b) sum -> 1 tanh + 1 STS per lane).
// ANTI-PHASE: co-resident CTA pairs are (bid, bid+148) under the contiguous-
// modular placement, so CTAs with bid >= 148 delay ~680 cyc at start; on
// every doubly-occupied SM one CTA's FMA burst then overlaps the other
// CTA's reduce/tanh/barrier tail instead of phase-locking with it.
// ---------------------------------------------------------------------------

#define HSTR 144                          // padded h row stride (floats)
#define SX_B_STRIDE (16 * IDIM)           // floats per batch per tile buffer
#define SX_BUF_BYTES (2 * 16 * IDIM * 4)  // 8192

struct StepCtx {
    u64t whh[2][16];   // [jj][2c+p]  k = 32kq + 4c + {0..3}
    u64t wih[2][8];    // [jj][2cc+p] rotated chunks
    int  xoff[4];      // rotated float offsets within 16-float i-slice
    int  kq36;         // h read offset for this lane's k-quarter
    int  stoff;        // final h store offset (floats) for this lane
    float biasF;       // bias of this lane's final (j,b)
    bool odd1, odd2;   // kq&1, kq&2 (butterfly select bits)
};

__device__ __forceinline__ void do_step(
    const StepCtx& C,
    const float* __restrict__ hr,
    float* __restrict__ hw,
    const float* __restrict__ xx)    // &sx[s][0][t][16*kq]
{
    const float* x0 = xx;
    const float* x1 = xx + SX_B_STRIDE;

    // ---- x-projection partials first (independent of h_t) ----
    u64t a00, a01, a10, a11;
    {
        ulonglong2 v0 = *(const ulonglong2*)(x0 + C.xoff[0]);
        ulonglong2 v1 = *(const ulonglong2*)(x1 + C.xoff[0]);
        a00 = fmul2(v0.x, C.wih[0][0]);
        a10 = fmul2(v0.x, C.wih[1][0]);
        a01 = fmul2(v1.x, C.wih[0][0]);
        a11 = fmul2(v1.x, C.wih[1][0]);
        a00 = ffma2(v0.y, C.wih[0][1], a00);
        a10 = ffma2(v0.y, C.wih[1][1], a10);
        a01 = ffma2(v1.y, C.wih[0][1], a01);
        a11 = ffma2(v1.y, C.wih[1][1], a11);
    }
    #pragma unroll
    for (int cc = 1; cc < 4; cc++) {
        ulonglong2 v0 = *(const ulonglong2*)(x0 + C.xoff[cc]);
        ulonglong2 v1 = *(const ulonglong2*)(x1 + C.xoff[cc]);
        a00 = ffma2(v0.x, C.wih[0][2 * cc],     a00);
        a10 = ffma2(v0.x, C.wih[1][2 * cc],     a10);
        a01 = ffma2(v1.x, C.wih[0][2 * cc],     a01);
        a11 = ffma2(v1.x, C.wih[1][2 * cc],     a11);
        a00 = ffma2(v0.y, C.wih[0][2 * cc + 1], a00);
        a10 = ffma2(v0.y, C.wih[1][2 * cc + 1], a10);
        a01 = ffma2(v1.y, C.wih[0][2 * cc + 1], a01);
        a11 = ffma2(v1.y, C.wih[1][2 * cc + 1], a11);
    }

    // ---- hidden-state FMAs ----
    const float* hb0 = hr + C.kq36;
    const float* hb1 = hr + HSTR + C.kq36;
    #pragma unroll
    for (int c = 0; c < 8; c++) {
        ulonglong2 h0 = *(const ulonglong2*)(hb0 + 4 * c);
        ulonglong2 h1 = *(const ulonglong2*)(hb1 + 4 * c);
        a00 = ffma2(h0.x, C.whh[0][2 * c],     a00);
        a10 = ffma2(h0.x, C.whh[1][2 * c],     a10);
        a00 = ffma2(h0.y, C.whh[0][2 * c + 1], a00);
        a10 = ffma2(h0.y, C.whh[1][2 * c + 1], a10);
        a01 = ffma2(h1.x, C.whh[0][2 * c],     a01);
        a11 = ffma2(h1.x, C.whh[1][2 * c],     a11);
        a01 = ffma2(h1.y, C.whh[0][2 * c + 1], a01);
        a11 = ffma2(h1.y, C.whh[1][2 * c + 1], a11);
    }

    float s00 = hadd2(a00), s01 = hadd2(a01);
    float s10 = hadd2(a10), s11 = hadd2(a11);

    // ---- butterfly-split reduce over the 4 kq lanes ----
    // round 1 (xor 8): keep b = (kq&1), give the other b
    float g0 = C.odd1 ? s00 : s01;
    float g1 = C.odd1 ? s10 : s11;
    float r0 = __shfl_xor_sync(0xffffffffu, g0, 8);
    float r1 = __shfl_xor_sync(0xffffffffu, g1, 8);
    float u0 = (C.odd1 ? s01 : s00) + r0;   // (j0, b=kq&1)
    float u1 = (C.odd1 ? s11 : s10) + r1;   // (j1, b=kq&1)
    // round 2 (xor 16): keep j = (kq&2 ? j1 : j0), give the other j
    float g  = C.odd2 ? u0 : u1;
    float r  = __shfl_xor_sync(0xffffffffu, g, 16);
    float sF = (C.odd2 ? u1 : u0) + r;      // finished (j,b) for this lane

    hw[C.stoff] = tanh_ap(sF + C.biasF);
    __syncthreads();
}

__global__ void __launch_bounds__(256, 2) rnn_fused(
    const float* __restrict__ x,
    const float* __restrict__ W_ih,
    const float* __restrict__ W_hh,
    const float* __restrict__ b_ih,
    const float* __restrict__ b_hh,
    const float* __restrict__ fc_w,
    const float* __restrict__ fc_b,
    float* __restrict__ out)
{
    __shared__ __align__(16) float sx[2][2][16][IDIM];   // 16 KB (double buffer)
    __shared__ __align__(16) float hbuf[2][2][HSTR];     // ping-pong h

    const int tid  = threadIdx.x;
    const int warp = tid >> 5, lane = tid & 31;
    const int kq   = lane >> 3;
    const int jl   = lane & 7;
    const int j0   = warp * 16 + jl;
    const int j1   = j0 + 8;
    const int row0 = blockIdx.x * 2;

    StepCtx C;
    C.kq36 = 36 * kq;
    C.odd1 = (kq & 1) != 0;
    C.odd2 = (kq & 2) != 0;
    {
        int jfin = (kq & 2) ? j1 : j0;
        int bfin = kq & 1;
        int jfp  = jfin + ((jfin >> 5) << 2);
        C.stoff  = bfin * HSTR + jfp;
        C.biasF  = b_ih[jfin] + b_hh[jfin];
    }

    // ---- load weights into registers ----
    #pragma unroll
    for (int jj = 0; jj < 2; jj++) {
        const float4* wr = (const float4*)(W_hh + (size_t)(jj ? j1 : j0) * HDIM + 32 * kq);
        #pragma unroll
        for (int c = 0; c < 8; c++) {
            float4 v = __ldg(wr + c);
            C.whh[jj][2 * c]     = pk(v.x, v.y);
            C.whh[jj][2 * c + 1] = pk(v.z, v.w);
        }
    }
    #pragma unroll
    for (int jj = 0; jj < 2; jj++) {
        const float4* wr = (const float4*)(W_ih + (size_t)(jj ? j1 : j0) * IDIM + 16 * kq);
        #pragma unroll
        for (int cc = 0; cc < 4; cc++) {
            int cl = (cc + kq) & 3;
            float4 v = __ldg(wr + cl);
            C.wih[jj][2 * cc]     = pk(v.x, v.y);
            C.wih[jj][2 * cc + 1] = pk(v.z, v.w);
        }
    }
    #pragma unroll
    for (int cc = 0; cc < 4; cc++) C.xoff[cc] = 4 * ((cc + kq) & 3);

    // ---- zero h buffers ----
    for (int i = tid; i < 2 * 2 * HSTR; i += 256) (&hbuf[0][0][0])[i] = 0.f;

    // ---- x staging slots (2 x 16B cp.async per thread per tile) ----
    const float* gsrc[2];
    unsigned     sdst[2];
    #pragma unroll
    for (int r = 0; r < 2; r++) {
        int idx = tid + 256 * r;          // 0..511
        int bb = idx >> 8;                // batch within CTA
        int rem = idx & 255;
        int tt = rem >> 4, f4 = rem & 15;
        gsrc[r] = x + ((size_t)(row0 + bb) * TSTEPS + tt) * IDIM + f4 * 4;
        sdst[r] = (unsigned)__cvta_generic_to_shared(&sx[0][bb][tt][f4 * 4]);
    }

    // stage tile 0 into buffer 0
    #pragma unroll
    for (int r = 0; r < 2; r++)
        asm volatile("cp.async.cg.shared.global [%0], [%1], 16;"
                     :: "r"(sdst[r]), "l"(gsrc[r]) : "memory");
    asm volatile("cp.async.commit_group;" ::: "memory");
    asm volatile("cp.async.wait_group 0;" ::: "memory");
    __syncthreads();

    // ---- anti-phase skew. Co-resident pairs are (bid, bid+148) under the
    //      contiguous-modular CTA->SM map, so delay the second wave-slot by
    //      ~half a step (168 dependent FMAs ~ 680 cyc). ----
    if (blockIdx.x >= 148) {
        float d = 1.0f;
        #pragma unroll 1
        for (int i = 0; i < 21; i++) {
            #pragma unroll
            for (int q = 0; q < 8; q++)
                asm volatile("fma.rn.f32 %0, %0, 0f3F800001, 0f33800000;" : "+f"(d));
        }
    }

    float* hA = &hbuf[0][0][0];
    float* hB = &hbuf[1][0][0];

    int s = 0;
    #pragma unroll 1
    for (int tile = 0; tile < TSTEPS / 16; tile++) {
        // prefetch next tile into the other buffer
        if (tile + 1 < TSTEPS / 16) {
            size_t goff = (size_t)(tile + 1) * 16 * IDIM;
            unsigned soff = (s ^ 1) * SX_BUF_BYTES;
            #pragma unroll
            for (int r = 0; r < 2; r++)
                asm volatile("cp.async.cg.shared.global [%0], [%1], 16;"
                             :: "r"(sdst[r] + soff), "l"(gsrc[r] + goff) : "memory");
        }
        asm volatile("cp.async.commit_group;" ::: "memory");

        const float* xb = &sx[s][0][0][16 * kq];
        #pragma unroll 1
        for (int m = 0; m < 4; m++) {
            const float* x0 = xb + (m * 4) * IDIM;
            do_step(C, hA, hB, x0);
            do_step(C, hB, hA, x0 + IDIM);
            do_step(C, hA, hB, x0 + 2 * IDIM);
            do_step(C, hB, hA, x0 + 3 * IDIM);
        }
        asm volatile("cp.async.wait_group 0;" ::: "memory");
        __syncthreads();
        s ^= 1;
    }

    // final h (after 1024 steps) lives in hbuf[0]
    if (warp < 2) {
        const int b = warp;
        float sum = 0.f;
        #pragma unroll
        for (int i = lane; i < HDIM; i += 32)
            sum += hbuf[0][b][i + ((i >> 5) << 2)] * fc_w[i];
        #pragma unroll
        for (int o = 16; o > 0; o >>= 1) sum += __shfl_xor_sync(0xffffffffu, sum, o);
        if (lane == 0) out[row0 + b] = 1.f / (1.f + __expf(-(sum + fc_b[0])));
    }
}

// ---------------------------------------------------------------------------
extern "C" void kernel_launch(void* const* d_in, const int* in_sizes, int n_in,
                              void* d_out, int out_size)
{
    const float* x    = (const float*)d_in[0];
    const float* W_ih = (const float*)d_in[1];
    const float* W_hh = (const float*)d_in[2];
    const float* b_ih = (const float*)d_in[3];
    const float* b_hh = (const float*)d_in[4];
    const float* fc_w = (const float*)d_in[5];
    const float* fc_b = (const float*)d_in[6];
    float* out = (float*)d_out;

    rnn_fused<<<BATCH / 2, 256>>>(x, W_ih, W_hh, b_ih, b_hh, fc_w, fc_b, out);
}

// round 9
// speedup vs baseline: 1.0546x; 1.0546x over previous
#include <cuda_runtime.h>
#include <cstdint>

#define BATCH 512
#define TSTEPS 1024
#define IDIM 64
#define HDIM 128

typedef unsigned long long u64t;

__device__ __forceinline__ u64t ffma2(u64t a, u64t b, u64t c) {
    u64t d;
    asm("fma.rn.f32x2 %0, %1, %2, %3;" : "=l"(d) : "l"(a), "l"(b), "l"(c));
    return d;
}
__device__ __forceinline__ u64t fmul2(u64t a, u64t b) {
    u64t d;
    asm("mul.rn.f32x2 %0, %1, %2;" : "=l"(d) : "l"(a), "l"(b));
    return d;
}
__device__ __forceinline__ u64t pk(float a, float b) {
    u64t r; asm("mov.b64 %0, {%1, %2};" : "=l"(r) : "f"(a), "f"(b)); return r;
}
__device__ __forceinline__ float hadd2(u64t v) {
    float x, y;
    asm("mov.b64 {%0, %1}, %2;" : "=f"(x), "=f"(y) : "l"(v));
    return x + y;
}
__device__ __forceinline__ float tanh_ap(float x) {
    float y; asm("tanh.approx.f32 %0, %1;" : "=f"(y) : "f"(x)); return y;
}

// ---------------------------------------------------------------------------
// Fully fused RNN: 256 CTAs x 256 threads, 2 batch rows/CTA, 2 CTAs/SM.
// Thread tiling: lane=(kq=lane>>3, jl=lane&7); warp w -> j0=w*16+jl, j1=j0+8.
// Register-pressure surgery vs R6 (suspected spills at the 128-reg cap):
//  - x rows staged PADDED (80 floats: 4-float pad per 16-float quarter), so
//    per-kq x LDS addresses are bank-disjoint with pure immediate offsets —
//    the xoff[4] rotation array and rotated-wih bookkeeping are gone.
//  - cp.async staging addresses are recomputed per 16-step tile instead of
//    held in gsrc[2]/sdst[2] across the whole kernel (~6 fewer live regs).
// Everything else (butterfly reduce, weights in regs, ping-pong h) as R6.
// ---------------------------------------------------------------------------

#define HSTR 144                           // padded h row stride (floats)
#define XROW 80                            // padded x row (floats): 4 * 20
#define SX_B_STRIDE (16 * XROW)            // 1280 floats per batch per buffer
#define SX_BUF_BYTES (2 * 16 * XROW * 4)   // 10240

struct StepCtx {
    u64t whh[2][16];   // [jj][2c+p]  k = 32kq + 4c + {0..3}
    u64t wih[2][8];    // [jj][2cc+p] i = 16kq + 4cc + {0..1}
    int  kq36;         // h read offset (36*kq) for this lane's k-quarter
    int  kq20;         // x read offset (20*kq) for this lane's i-quarter
    int  stoff;        // final h store offset (floats) for this lane
    float biasF;       // bias of this lane's final (j,b)
    bool odd1, odd2;   // kq&1, kq&2 (butterfly select bits)
};

__device__ __forceinline__ void do_step(
    const StepCtx& C,
    const float* __restrict__ hr,
    float* __restrict__ hw,
    const float* __restrict__ xx)    // &sx[s][0][t][0]
{
    const float* x0 = xx + C.kq20;
    const float* x1 = x0 + SX_B_STRIDE;

    // ---- x-projection partials first (independent of h_t) ----
    u64t a00, a01, a10, a11;
    {
        ulonglong2 v0 = *(const ulonglong2*)(x0);
        ulonglong2 v1 = *(const ulonglong2*)(x1);
        a00 = fmul2(v0.x, C.wih[0][0]);
        a10 = fmul2(v0.x, C.wih[1][0]);
        a01 = fmul2(v1.x, C.wih[0][0]);
        a11 = fmul2(v1.x, C.wih[1][0]);
        a00 = ffma2(v0.y, C.wih[0][1], a00);
        a10 = ffma2(v0.y, C.wih[1][1], a10);
        a01 = ffma2(v1.y, C.wih[0][1], a01);
        a11 = ffma2(v1.y, C.wih[1][1], a11);
    }
    #pragma unroll
    for (int cc = 1; cc < 4; cc++) {
        ulonglong2 v0 = *(const ulonglong2*)(x0 + 4 * cc);
        ulonglong2 v1 = *(const ulonglong2*)(x1 + 4 * cc);
        a00 = ffma2(v0.x, C.wih[0][2 * cc],     a00);
        a10 = ffma2(v0.x, C.wih[1][2 * cc],     a10);
        a01 = ffma2(v1.x, C.wih[0][2 * cc],     a01);
        a11 = ffma2(v1.x, C.wih[1][2 * cc],     a11);
        a00 = ffma2(v0.y, C.wih[0][2 * cc + 1], a00);
        a10 = ffma2(v0.y, C.wih[1][2 * cc + 1], a10);
        a01 = ffma2(v1.y, C.wih[0][2 * cc + 1], a01);
        a11 = ffma2(v1.y, C.wih[1][2 * cc + 1], a11);
    }

    // ---- hidden-state FMAs ----
    const float* hb0 = hr + C.kq36;
    const float* hb1 = hb0 + HSTR;
    #pragma unroll
    for (int c = 0; c < 8; c++) {
        ulonglong2 h0 = *(const ulonglong2*)(hb0 + 4 * c);
        ulonglong2 h1 = *(const ulonglong2*)(hb1 + 4 * c);
        a00 = ffma2(h0.x, C.whh[0][2 * c],     a00);
        a10 = ffma2(h0.x, C.whh[1][2 * c],     a10);
        a00 = ffma2(h0.y, C.whh[0][2 * c + 1], a00);
        a10 = ffma2(h0.y, C.whh[1][2 * c + 1], a10);
        a01 = ffma2(h1.x, C.whh[0][2 * c],     a01);
        a11 = ffma2(h1.x, C.whh[1][2 * c],     a11);
        a01 = ffma2(h1.y, C.whh[0][2 * c + 1], a01);
        a11 = ffma2(h1.y, C.whh[1][2 * c + 1], a11);
    }

    float s00 = hadd2(a00), s01 = hadd2(a01);
    float s10 = hadd2(a10), s11 = hadd2(a11);

    // ---- butterfly-split reduce over the 4 kq lanes ----
    float g0 = C.odd1 ? s00 : s01;
    float g1 = C.odd1 ? s10 : s11;
    float r0 = __shfl_xor_sync(0xffffffffu, g0, 8);
    float r1 = __shfl_xor_sync(0xffffffffu, g1, 8);
    float u0 = (C.odd1 ? s01 : s00) + r0;   // (j0, b=kq&1)
    float u1 = (C.odd1 ? s11 : s10) + r1;   // (j1, b=kq&1)
    float g  = C.odd2 ? u0 : u1;
    float r  = __shfl_xor_sync(0xffffffffu, g, 16);
    float sF = (C.odd2 ? u1 : u0) + r;      // finished (j,b) for this lane

    hw[C.stoff] = tanh_ap(sF + C.biasF);
    __syncthreads();
}

// Stage one 16-step x tile via cp.async (addresses recomputed, not cached).
__device__ __forceinline__ void stage_tile(
    const float* __restrict__ xg, int row0, int tid, unsigned sx0,
    int sbuf, int tile)
{
    #pragma unroll
    for (int r = 0; r < 2; r++) {
        int idx = tid + 256 * r;          // 0..511
        int bb  = idx >> 8;               // batch within CTA
        int rem = idx & 255;
        int tt  = rem >> 4, f4 = rem & 15;
        const float* src = xg + ((size_t)(row0 + bb) * TSTEPS + tile * 16 + tt) * IDIM + f4 * 4;
        unsigned dst = sx0 + (unsigned)sbuf * SX_BUF_BYTES
                     + (unsigned)(bb * SX_B_STRIDE + tt * XROW + (f4 >> 2) * 20 + (f4 & 3) * 4) * 4u;
        asm volatile("cp.async.cg.shared.global [%0], [%1], 16;"
                     :: "r"(dst), "l"(src) : "memory");
    }
}

__global__ void __launch_bounds__(256, 2) rnn_fused(
    const float* __restrict__ x,
    const float* __restrict__ W_ih,
    const float* __restrict__ W_hh,
    const float* __restrict__ b_ih,
    const float* __restrict__ b_hh,
    const float* __restrict__ fc_w,
    const float* __restrict__ fc_b,
    float* __restrict__ out)
{
    __shared__ __align__(16) float sx[2][2][16][XROW];   // 20 KB (double buffer)
    __shared__ __align__(16) float hbuf[2][2][HSTR];     // ping-pong h

    const int tid  = threadIdx.x;
    const int warp = tid >> 5, lane = tid & 31;
    const int kq   = lane >> 3;
    const int jl   = lane & 7;
    const int j0   = warp * 16 + jl;
    const int j1   = j0 + 8;
    const int row0 = blockIdx.x * 2;

    StepCtx C;
    C.kq36 = 36 * kq;
    C.kq20 = 20 * kq;
    C.odd1 = (kq & 1) != 0;
    C.odd2 = (kq & 2) != 0;
    {
        int jfin = (kq & 2) ? j1 : j0;
        int bfin = kq & 1;
        int jfp  = jfin + ((jfin >> 5) << 2);
        C.stoff  = bfin * HSTR + jfp;
        C.biasF  = b_ih[jfin] + b_hh[jfin];
    }

    // ---- load weights into registers ----
    #pragma unroll
    for (int jj = 0; jj < 2; jj++) {
        const float4* wr = (const float4*)(W_hh + (size_t)(jj ? j1 : j0) * HDIM + 32 * kq);
        #pragma unroll
        for (int c = 0; c < 8; c++) {
            float4 v = __ldg(wr + c);
            C.whh[jj][2 * c]     = pk(v.x, v.y);
            C.whh[jj][2 * c + 1] = pk(v.z, v.w);
        }
    }
    #pragma unroll
    for (int jj = 0; jj < 2; jj++) {
        const float4* wr = (const float4*)(W_ih + (size_t)(jj ? j1 : j0) * IDIM + 16 * kq);
        #pragma unroll
        for (int cc = 0; cc < 4; cc++) {
            float4 v = __ldg(wr + cc);
            C.wih[jj][2 * cc]     = pk(v.x, v.y);
            C.wih[jj][2 * cc + 1] = pk(v.z, v.w);
        }
    }

    // ---- zero h buffers ----
    for (int i = tid; i < 2 * 2 * HSTR; i += 256) (&hbuf[0][0][0])[i] = 0.f;

    const unsigned sx0 = (unsigned)__cvta_generic_to_shared(&sx[0][0][0][0]);

    // stage tile 0 into buffer 0
    stage_tile(x, row0, tid, sx0, 0, 0);
    asm volatile("cp.async.commit_group;" ::: "memory");
    asm volatile("cp.async.wait_group 0;" ::: "memory");
    __syncthreads();

    float* hA = &hbuf[0][0][0];
    float* hB = &hbuf[1][0][0];

    int s = 0;
    #pragma unroll 1
    for (int tile = 0; tile < TSTEPS / 16; tile++) {
        // prefetch next tile into the other buffer
        if (tile + 1 < TSTEPS / 16)
            stage_tile(x, row0, tid, sx0, s ^ 1, tile + 1);
        asm volatile("cp.async.commit_group;" ::: "memory");

        const float* xb = &sx[s][0][0][0];
        #pragma unroll 1
        for (int m = 0; m < 4; m++) {
            const float* xt = xb + (m * 4) * XROW;
            do_step(C, hA, hB, xt);
            do_step(C, hB, hA, xt + XROW);
            do_step(C, hA, hB, xt + 2 * XROW);
            do_step(C, hB, hA, xt + 3 * XROW);
        }
        asm volatile("cp.async.wait_group 0;" ::: "memory");
        __syncthreads();
        s ^= 1;
    }

    // final h (after 1024 steps) lives in hbuf[0]
    if (warp < 2) {
        const int b = warp;
        float sum = 0.f;
        #pragma unroll
        for (int i = lane; i < HDIM; i += 32)
            sum += hbuf[0][b][i + ((i >> 5) << 2)] * fc_w[i];
        #pragma unroll
        for (int o = 16; o > 0; o >>= 1) sum += __shfl_xor_sync(0xffffffffu, sum, o);
        if (lane == 0) out[row0 + b] = 1.f / (1.f + __expf(-(sum + fc_b[0])));
    }
}

// ---------------------------------------------------------------------------
extern "C" void kernel_launch(void* const* d_in, const int* in_sizes, int n_in,
                              void* d_out, int out_size)
{
    const float* x    = (const float*)d_in[0];
    const float* W_ih = (const float*)d_in[1];
    const float* W_hh = (const float*)d_in[2];
    const float* b_ih = (const float*)d_in[3];
    const float* b_hh = (const float*)d_in[4];
    const float* fc_w = (const float*)d_in[5];
    const float* fc_b = (const float*)d_in[6];
    float* out = (float*)d_out;

    rnn_fused<<<BATCH / 2, 256>>>(x, W_ih, W_hh, b_ih, b_hh, fc_w, fc_b, out);
}